// round 12
// baseline (speedup 1.0000x reference)
#include <cuda_runtime.h>
#include <cuda_bf16.h>
#include <math.h>

// Problem constants (fixed shapes for this problem)
#define NBOX  4096
#define IMG_H 512
#define IMG_W 512
#define IMG_C 64

typedef unsigned long long ull;

// Scratch (no cudaMalloc allowed)
__device__ float g_x1[NBOX * 2048];   // conv2 output, flattened
__device__ float g_h1[NBOX * 512];    // d1 output
__device__ float g_h2[NBOX * 512];    // d2 output

// ---------------- packed f32x2 helpers (Blackwell FFMA2) ----------------
__device__ __forceinline__ ull fma2(ull a, ull b, ull c) {
    ull d;
    asm("fma.rn.f32x2 %0, %1, %2, %3;" : "=l"(d) : "l"(a), "l"(b), "l"(c));
    return d;
}
__device__ __forceinline__ ull pack2(float lo, float hi) {
    ull d;
    asm("mov.b64 %0, {%1, %2};" : "=l"(d) : "r"(__float_as_uint(lo)), "r"(__float_as_uint(hi)));
    return d;
}
__device__ __forceinline__ ull dup2(float v) { return pack2(v, v); }
__device__ __forceinline__ void unpack2(ull p, float& lo, float& hi) {
    unsigned int a, b;
    asm("mov.b64 {%0, %1}, %2;" : "=r"(a), "=r"(b) : "l"(p));
    lo = __uint_as_float(a); hi = __uint_as_float(b);
}

// ---------------------------------------------------------------------------
// K1: fused crop_and_resize * proposal -> conv1(s2,relu) -> conv2(s2,relu)
// One CTA per box. smem: x0[16][16][64] (64KB) + c1[8][8][128] (32KB) = 96KB.
//
// conv1: thread = 4 oc x 8 positions; conv2: thread = 2 oc x 4 positions.
// Tap x ic loops are FLATTENED and weight LDGs are register-prefetched one
// iteration ahead so L2 latency hides behind the previous iteration's FMAs.
// ---------------------------------------------------------------------------
__global__ __launch_bounds__(256, 2) void k_backbone(
    const float* __restrict__ feat, const float* __restrict__ prop,
    const float* __restrict__ boxes, const int* __restrict__ bidx,
    const float* __restrict__ w1, const float* __restrict__ b1,
    const float* __restrict__ w2, const float* __restrict__ b2,
    float* __restrict__ xout)
{
    extern __shared__ float smem[];
    float* s_x0 = smem;                 // 16*16*64 = 16384 floats
    float* s_c1 = smem + 16 * 16 * 64;  // 8*8*128  =  8192 floats

    const int box = blockIdx.x;
    const int t = threadIdx.x;

    const float by1 = boxes[box * 4 + 0];
    const float bx1 = boxes[box * 4 + 1];
    const float by2 = boxes[box * 4 + 2];
    const float bx2 = boxes[box * 4 + 3];
    const int b = bidx[box];

    // ---- Stage 1: bilinear crop (features) * bilinear crop (proposal) ----
    {
        const int gy = t >> 4, gx = t & 15;
        const float ys = (by1 + ((float)gy / 15.f) * (by2 - by1)) * 511.f;
        const float xs = (bx1 + ((float)gx / 15.f) * (bx2 - bx1)) * 511.f;
        const float y0f = floorf(ys), x0f = floorf(xs);
        const float wy = ys - y0f, wx = xs - x0f;
        int iy0 = (int)y0f; iy0 = iy0 < 0 ? 0 : (iy0 > 511 ? 511 : iy0);
        int ix0 = (int)x0f; ix0 = ix0 < 0 ? 0 : (ix0 > 511 ? 511 : ix0);
        const int iy1 = iy0 + 1 > 511 ? 511 : iy0 + 1;
        const int ix1 = ix0 + 1 > 511 ? 511 : ix0 + 1;

        const size_t base = (size_t)b * IMG_H * IMG_W;
        const float p00 = prop[base + (size_t)iy0 * IMG_W + ix0];
        const float p01 = prop[base + (size_t)iy0 * IMG_W + ix1];
        const float p10 = prop[base + (size_t)iy1 * IMG_W + ix0];
        const float p11 = prop[base + (size_t)iy1 * IMG_W + ix1];
        const float omwx = 1.f - wx, omwy = 1.f - wy;
        const float pv = (p00 * omwx + p01 * wx) * omwy
                       + (p10 * omwx + p11 * wx) * wy;

        const float4* f00 = (const float4*)(feat + (base + (size_t)iy0 * IMG_W + ix0) * IMG_C);
        const float4* f01 = (const float4*)(feat + (base + (size_t)iy0 * IMG_W + ix1) * IMG_C);
        const float4* f10 = (const float4*)(feat + (base + (size_t)iy1 * IMG_W + ix0) * IMG_C);
        const float4* f11 = (const float4*)(feat + (base + (size_t)iy1 * IMG_W + ix1) * IMG_C);
        float4* dst = (float4*)(s_x0 + t * 64);
        #pragma unroll
        for (int cb = 0; cb < 16; cb++) {
            float4 a = f00[cb], c = f01[cb], d = f10[cb], e = f11[cb];
            float4 r;
            r.x = ((a.x * omwx + c.x * wx) * omwy + (d.x * omwx + e.x * wx) * wy) * pv;
            r.y = ((a.y * omwx + c.y * wx) * omwy + (d.y * omwx + e.y * wx) * wy) * pv;
            r.z = ((a.z * omwx + c.z * wx) * omwy + (d.z * omwx + e.z * wx) * wy) * pv;
            r.w = ((a.w * omwx + c.w * wx) * omwy + (d.w * omwx + e.w * wx) * wy) * pv;
            dst[cb] = r;
        }
    }
    __syncthreads();

    // ---- Stage 2: conv1 3x3 s2 SAME (pad lo=0, hi=1), 64->128, relu ----
    // thread: g1 = t&31 -> ocs [g1*4, g1*4+4) (2 packed pairs)
    //         s1 = t>>5 -> 8 positions [s1*8, s1*8+8)  (warp-uniform -> LDS bcast)
    // Flattened 9 taps x 16 ic-blocks = 144 iterations, weights prefetched +1.
    {
        const int g1 = t & 31;
        const int oc0 = g1 * 4;
        const int s1 = t >> 5;

        ull acc[8][2];
        {
            float4 bb = __ldg((const float4*)(b1 + oc0));
            ull p0 = pack2(bb.x, bb.y), p1 = pack2(bb.z, bb.w);
            #pragma unroll
            for (int j = 0; j < 8; j++) { acc[j][0] = p0; acc[j][1] = p1; }
        }

        int ib[8];
        ulonglong2 nw0, nw1, nw2, nw3;
        {
            const float* wb = w1 + oc0;   // it=0: tap 0, ic 0
            nw0 = __ldg((const ulonglong2*)(wb));
            nw1 = __ldg((const ulonglong2*)(wb + 128));
            nw2 = __ldg((const ulonglong2*)(wb + 256));
            nw3 = __ldg((const ulonglong2*)(wb + 384));
        }

        #pragma unroll 1
        for (int it = 0; it < 144; it++) {
            const int tap = it >> 4;
            const int ic = (it & 15) << 2;
            if ((it & 15) == 0) {
                const int ky = tap / 3, kx = tap - ky * 3;
                #pragma unroll
                for (int j = 0; j < 8; j++) {
                    const int pos = s1 * 8 + j;
                    const int oy = pos >> 3, ox = pos & 7;
                    const int iy = 2 * oy + ky, ix = 2 * ox + kx;
                    ib[j] = (iy < 16 && ix < 16) ? (iy * 16 + ix) * 64 : -1;
                }
            }
            const ulonglong2 w0 = nw0, w1v = nw1, w2v = nw2, w3v = nw3;
            if (it < 143) {
                const int nit = it + 1;
                const float* wb = w1 + (size_t)(((nit >> 4) << 6) + ((nit & 15) << 2)) * 128 + oc0;
                nw0 = __ldg((const ulonglong2*)(wb));
                nw1 = __ldg((const ulonglong2*)(wb + 128));
                nw2 = __ldg((const ulonglong2*)(wb + 256));
                nw3 = __ldg((const ulonglong2*)(wb + 384));
            }
            #pragma unroll
            for (int j = 0; j < 8; j++) {
                if (ib[j] >= 0) {
                    float4 v = *(const float4*)(s_x0 + ib[j] + ic);
                    ull dx = dup2(v.x), dy = dup2(v.y), dz = dup2(v.z), dw = dup2(v.w);
                    acc[j][0] = fma2(dx, w0.x, acc[j][0]);
                    acc[j][1] = fma2(dx, w0.y, acc[j][1]);
                    acc[j][0] = fma2(dy, w1v.x, acc[j][0]);
                    acc[j][1] = fma2(dy, w1v.y, acc[j][1]);
                    acc[j][0] = fma2(dz, w2v.x, acc[j][0]);
                    acc[j][1] = fma2(dz, w2v.y, acc[j][1]);
                    acc[j][0] = fma2(dw, w3v.x, acc[j][0]);
                    acc[j][1] = fma2(dw, w3v.y, acc[j][1]);
                }
            }
        }
        #pragma unroll
        for (int j = 0; j < 8; j++) {
            const int pos = s1 * 8 + j;
            float v0, v1, v2, v3;
            unpack2(acc[j][0], v0, v1); unpack2(acc[j][1], v2, v3);
            *(float4*)(s_c1 + pos * 128 + oc0) =
                make_float4(fmaxf(v0, 0.f), fmaxf(v1, 0.f),
                            fmaxf(v2, 0.f), fmaxf(v3, 0.f));
        }
    }
    __syncthreads();

    // ---- Stage 3: conv2 3x3 s2 SAME (pad lo=0, hi=1), 128->128, relu ----
    // thread: p2 = t&63 -> oc pair [p2*2, p2*2+2), s2 = t>>6 -> 4 positions.
    // Flattened 9 taps x 32 ic-blocks = 288 iterations, weights prefetched +1.
    {
        const int p2 = t & 63;
        const int oc0 = p2 * 2;
        const int s2 = t >> 6;

        ull acc2[4];
        {
            ull bb = __ldg((const ull*)(b2 + oc0));
            #pragma unroll
            for (int j = 0; j < 4; j++) acc2[j] = bb;
        }

        int ib[4];
        ull nv0, nv1, nv2, nv3;
        {
            const float* wb = w2 + oc0;   // it=0: tap 0, ic 0
            nv0 = __ldg((const ull*)(wb));
            nv1 = __ldg((const ull*)(wb + 128));
            nv2 = __ldg((const ull*)(wb + 256));
            nv3 = __ldg((const ull*)(wb + 384));
        }

        #pragma unroll 1
        for (int it = 0; it < 288; it++) {
            const int tap = it >> 5;
            const int ic = (it & 31) << 2;
            if ((it & 31) == 0) {
                const int ky = tap / 3, kx = tap - ky * 3;
                #pragma unroll
                for (int j = 0; j < 4; j++) {
                    const int pos = s2 * 4 + j;
                    const int oy = pos >> 2, ox = pos & 3;
                    const int iy = 2 * oy + ky, ix = 2 * ox + kx;
                    ib[j] = (iy < 8 && ix < 8) ? (iy * 8 + ix) * 128 : -1;
                }
            }
            const ull w0 = nv0, w1v = nv1, w2v = nv2, w3v = nv3;
            if (it < 287) {
                const int nit = it + 1;
                const float* wb = w2 + (size_t)(((nit >> 5) << 7) + ((nit & 31) << 2)) * 128 + oc0;
                nv0 = __ldg((const ull*)(wb));
                nv1 = __ldg((const ull*)(wb + 128));
                nv2 = __ldg((const ull*)(wb + 256));
                nv3 = __ldg((const ull*)(wb + 384));
            }
            #pragma unroll
            for (int j = 0; j < 4; j++) {
                if (ib[j] >= 0) {
                    float4 v = *(const float4*)(s_c1 + ib[j] + ic);
                    acc2[j] = fma2(dup2(v.x), w0, acc2[j]);
                    acc2[j] = fma2(dup2(v.y), w1v, acc2[j]);
                    acc2[j] = fma2(dup2(v.z), w2v, acc2[j]);
                    acc2[j] = fma2(dup2(v.w), w3v, acc2[j]);
                }
            }
        }
        float* o = xout + (size_t)box * 2048;
        #pragma unroll
        for (int j = 0; j < 4; j++) {
            const int pos = s2 * 4 + j;
            float v0, v1;
            unpack2(acc2[j], v0, v1);
            *(float2*)(o + pos * 128 + oc0) =
                make_float2(fmaxf(v0, 0.f), fmaxf(v1, 0.f));
        }
    }
}

// ---------------------------------------------------------------------------
// GEMM: C[M,N] = act(A[M,K] @ B[K,N] + bias). 64x64 tile, 256 threads, 4x4/thr.
// Register double-buffered global loads (hide LDG latency behind compute).
// ---------------------------------------------------------------------------
template <int RELU>
__global__ __launch_bounds__(256) void k_gemm(
    const float* __restrict__ A, const float* __restrict__ Bm,
    const float* __restrict__ bias, float* __restrict__ Cm,
    int M, int N, int K)
{
    __shared__ float As[16][68];   // [k][m] — m contiguous
    __shared__ float Bs[16][68];   // [k][n] — n contiguous
    const int tid = threadIdx.x;
    const int m0 = blockIdx.x * 64, n0 = blockIdx.y * 64;
    const int tr = tid >> 4, tc = tid & 15;
    const int lam = tid >> 2, lak = (tid & 3) * 4;
    const int lbk = tid >> 4, lbn = (tid & 15) * 4;

    ull accp[2][4];
    #pragma unroll
    for (int i = 0; i < 2; i++)
        #pragma unroll
        for (int j = 0; j < 4; j++) accp[i][j] = 0ull;

    const float* Ap = A + (size_t)(m0 + lam) * K + lak;
    const float* Bp = Bm + (size_t)lbk * N + n0 + lbn;

    float4 a = *(const float4*)(Ap);
    float4 bv = *(const float4*)(Bp);

    for (int k0 = 0; k0 < K; k0 += 16) {
        __syncthreads();
        As[lak + 0][lam] = a.x; As[lak + 1][lam] = a.y;
        As[lak + 2][lam] = a.z; As[lak + 3][lam] = a.w;
        *(float4*)&Bs[lbk][lbn] = bv;
        __syncthreads();
        if (k0 + 16 < K) {   // prefetch next tile while computing this one
            a = *(const float4*)(Ap + k0 + 16);
            bv = *(const float4*)(Bp + (size_t)(k0 + 16) * N);
        }
        #pragma unroll
        for (int k = 0; k < 16; k++) {
            ulonglong2 ap = *(const ulonglong2*)&As[k][tr * 4];
            float4 bb = *(const float4*)&Bs[k][tc * 4];
            ull b0 = dup2(bb.x), b1 = dup2(bb.y), b2 = dup2(bb.z), b3 = dup2(bb.w);
            accp[0][0] = fma2(ap.x, b0, accp[0][0]);
            accp[0][1] = fma2(ap.x, b1, accp[0][1]);
            accp[0][2] = fma2(ap.x, b2, accp[0][2]);
            accp[0][3] = fma2(ap.x, b3, accp[0][3]);
            accp[1][0] = fma2(ap.y, b0, accp[1][0]);
            accp[1][1] = fma2(ap.y, b1, accp[1][1]);
            accp[1][2] = fma2(ap.y, b2, accp[1][2]);
            accp[1][3] = fma2(ap.y, b3, accp[1][3]);
        }
    }

    float4 bvq = __ldg((const float4*)(bias + n0 + tc * 4));
    float bias4[4] = {bvq.x, bvq.y, bvq.z, bvq.w};
    #pragma unroll
    for (int ih = 0; ih < 2; ih++) {
        float r0[4], r1[4];
        #pragma unroll
        for (int j = 0; j < 4; j++) unpack2(accp[ih][j], r0[j], r1[j]);
        #pragma unroll
        for (int j = 0; j < 4; j++) {
            r0[j] += bias4[j]; r1[j] += bias4[j];
            if (RELU) { r0[j] = fmaxf(r0[j], 0.f); r1[j] = fmaxf(r1[j], 0.f); }
        }
        const int row0 = m0 + tr * 4 + 2 * ih;
        *(float4*)(Cm + (size_t)row0 * N + n0 + tc * 4) =
            make_float4(r0[0], r0[1], r0[2], r0[3]);
        *(float4*)(Cm + (size_t)(row0 + 1) * N + n0 + tc * 4) =
            make_float4(r1[0], r1[1], r1[2], r1[3]);
    }
}

// ---------------------------------------------------------------------------
// K4: heads — reg/score dots (warp per box), class select, box decode.
// out = [scores (Nb) | regressions (Nb*4) | bboxes (Nb*4)]
// ---------------------------------------------------------------------------
__global__ __launch_bounds__(256) void k_heads(
    const float* __restrict__ X, const float* __restrict__ boxes,
    const int* __restrict__ cls, const float* __restrict__ regw,
    const float* __restrict__ regb, const float* __restrict__ scw,
    const float* __restrict__ scb, float* __restrict__ out, int Nb)
{
    const int gw = (blockIdx.x * blockDim.x + threadIdx.x) >> 5;
    const int lane = threadIdx.x & 31;
    if (gw >= Nb) return;
    const float* x = X + (size_t)gw * 512;

    float acc[12], sc[3];
    #pragma unroll
    for (int c = 0; c < 12; c++) acc[c] = 0.f;
    #pragma unroll
    for (int c = 0; c < 3; c++) sc[c] = 0.f;

    for (int j = lane; j < 512; j += 32) {
        float xv = x[j];
        const float* wr = regw + j * 12;
        #pragma unroll
        for (int c = 0; c < 12; c++) acc[c] = fmaf(xv, __ldg(wr + c), acc[c]);
        const float* ws = scw + j * 3;
        #pragma unroll
        for (int c = 0; c < 3; c++) sc[c] = fmaf(xv, __ldg(ws + c), sc[c]);
    }
    #pragma unroll
    for (int c = 0; c < 12; c++)
        for (int s = 16; s; s >>= 1) acc[c] += __shfl_xor_sync(0xffffffffu, acc[c], s);
    #pragma unroll
    for (int c = 0; c < 3; c++)
        for (int s = 16; s; s >>= 1) sc[c] += __shfl_xor_sync(0xffffffffu, sc[c], s);

    if (lane == 0) {
        const int cl = cls[gw];
        float r[4];
        #pragma unroll
        for (int k = 0; k < 4; k++) {
            float v = (cl == 0) ? acc[k] : (cl == 1) ? acc[4 + k] : acc[8 + k];
            r[k] = v + regb[cl * 4 + k];
        }
        float score = ((cl == 0) ? sc[0] : (cl == 1) ? sc[1] : sc[2]) + scb[cl];

        const float y1 = boxes[gw * 4 + 0], x1 = boxes[gw * 4 + 1];
        const float y2 = boxes[gw * 4 + 2], x2 = boxes[gw * 4 + 3];
        const float h = y2 - y1, w = x2 - x1;
        const float cy = y1 + 0.5f * h + r[0] * h;
        const float cx = x1 + 0.5f * w + r[1] * w;
        const float nh = h * expf(r[2]);
        const float nw = w * expf(r[3]);

        out[gw] = score;
        float* ro = out + Nb + (size_t)gw * 4;
        ro[0] = r[0]; ro[1] = r[1]; ro[2] = r[2]; ro[3] = r[3];
        float* bo = out + (size_t)Nb * 5 + (size_t)gw * 4;
        bo[0] = cy - 0.5f * nh; bo[1] = cx - 0.5f * nw;
        bo[2] = cy + 0.5f * nh; bo[3] = cx + 0.5f * nw;
    }
}

// ---------------------------------------------------------------------------
extern "C" void kernel_launch(void* const* d_in, const int* in_sizes, int n_in,
                              void* d_out, int out_size)
{
    const float* features = (const float*)d_in[0];
    const float* proposal = (const float*)d_in[1];
    const float* bboxes   = (const float*)d_in[2];
    const int*   box_idx  = (const int*)d_in[3];
    const int*   cls      = (const int*)d_in[4];
    const float* c1w      = (const float*)d_in[5];
    const float* c1b      = (const float*)d_in[6];
    const float* c2w      = (const float*)d_in[7];
    const float* c2b      = (const float*)d_in[8];
    const float* d1w      = (const float*)d_in[9];
    const float* d1b      = (const float*)d_in[10];
    const float* d2w      = (const float*)d_in[11];
    const float* d2b      = (const float*)d_in[12];
    const float* regw     = (const float*)d_in[13];
    const float* regb     = (const float*)d_in[14];
    const float* scw      = (const float*)d_in[15];
    const float* scb      = (const float*)d_in[16];
    float* out = (float*)d_out;

    const int Nb = in_sizes[3];  // number of boxes (4096)

    void *px1, *ph1, *ph2;
    cudaGetSymbolAddress(&px1, g_x1);
    cudaGetSymbolAddress(&ph1, g_h1);
    cudaGetSymbolAddress(&ph2, g_h2);

    const int smem_k1 = (16 * 16 * 64 + 8 * 8 * 128) * 4;  // 98304 bytes
    cudaFuncSetAttribute(k_backbone, cudaFuncAttributeMaxDynamicSharedMemorySize, smem_k1);

    k_backbone<<<Nb, 256, smem_k1>>>(features, proposal, bboxes, box_idx,
                                     c1w, c1b, c2w, c2b, (float*)px1);

    k_gemm<1><<<dim3(Nb / 64, 512 / 64), 256>>>((const float*)px1, d1w, d1b,
                                                (float*)ph1, Nb, 512, 2048);
    k_gemm<1><<<dim3(Nb / 64, 512 / 64), 256>>>((const float*)ph1, d2w, d2b,
                                                (float*)ph2, Nb, 512, 512);

    k_heads<<<(Nb * 32 + 255) / 256, 256>>>((const float*)ph2, bboxes, cls,
                                            regw, regb, scw, scb, out, Nb);
}

// round 17
// speedup vs baseline: 1.3079x; 1.3079x over previous
#include <cuda_runtime.h>
#include <cuda_bf16.h>
#include <math.h>

// Problem constants (fixed shapes for this problem)
#define NBOX  4096
#define IMG_H 512
#define IMG_W 512
#define IMG_C 64

typedef unsigned long long ull;

// Scratch (no cudaMalloc allowed)
__device__ float g_x1[NBOX * 2048];   // conv2 output, flattened
__device__ float g_h1[NBOX * 512];    // d1 output
__device__ float g_h2[NBOX * 512];    // d2 output

// ---------------- packed f32x2 helpers (Blackwell FFMA2) ----------------
__device__ __forceinline__ ull fma2(ull a, ull b, ull c) {
    ull d;
    asm("fma.rn.f32x2 %0, %1, %2, %3;" : "=l"(d) : "l"(a), "l"(b), "l"(c));
    return d;
}
__device__ __forceinline__ ull pack2(float lo, float hi) {
    ull d;
    asm("mov.b64 %0, {%1, %2};" : "=l"(d) : "r"(__float_as_uint(lo)), "r"(__float_as_uint(hi)));
    return d;
}
__device__ __forceinline__ ull dup2(float v) { return pack2(v, v); }
__device__ __forceinline__ void unpack2(ull p, float& lo, float& hi) {
    unsigned int a, b;
    asm("mov.b64 {%0, %1}, %2;" : "=r"(a), "=r"(b) : "l"(p));
    lo = __uint_as_float(a); hi = __uint_as_float(b);
}

// Dummy kernel: shifts ncu's -s 5 skip window so k_backbone gets profiled.
__global__ void k_nop() {}

// ---------------------------------------------------------------------------
// K1: fused crop_and_resize * proposal -> conv1(s2,relu) -> conv2(s2,relu)
// One CTA per box. smem: x0[16][16][64] (64KB) + c1[8][8][128] (32KB) = 96KB.
//
// conv1: thread = 4 oc x 8 positions; conv2: thread = 2 oc x 4 positions.
// ic loops unrolled x2 so ptxas batches weight LDGs (MLP 8) and covers each
// half's L2 latency with the other half's FMAs. No persistent prefetch regs.
// ---------------------------------------------------------------------------
__global__ __launch_bounds__(256, 2) void k_backbone(
    const float* __restrict__ feat, const float* __restrict__ prop,
    const float* __restrict__ boxes, const int* __restrict__ bidx,
    const float* __restrict__ w1, const float* __restrict__ b1,
    const float* __restrict__ w2, const float* __restrict__ b2,
    float* __restrict__ xout)
{
    extern __shared__ float smem[];
    float* s_x0 = smem;                 // 16*16*64 = 16384 floats
    float* s_c1 = smem + 16 * 16 * 64;  // 8*8*128  =  8192 floats

    const int box = blockIdx.x;
    const int t = threadIdx.x;

    const float by1 = boxes[box * 4 + 0];
    const float bx1 = boxes[box * 4 + 1];
    const float by2 = boxes[box * 4 + 2];
    const float bx2 = boxes[box * 4 + 3];
    const int b = bidx[box];

    // ---- Stage 1: bilinear crop (features) * bilinear crop (proposal) ----
    {
        const int gy = t >> 4, gx = t & 15;
        const float ys = (by1 + ((float)gy / 15.f) * (by2 - by1)) * 511.f;
        const float xs = (bx1 + ((float)gx / 15.f) * (bx2 - bx1)) * 511.f;
        const float y0f = floorf(ys), x0f = floorf(xs);
        const float wy = ys - y0f, wx = xs - x0f;
        int iy0 = (int)y0f; iy0 = iy0 < 0 ? 0 : (iy0 > 511 ? 511 : iy0);
        int ix0 = (int)x0f; ix0 = ix0 < 0 ? 0 : (ix0 > 511 ? 511 : ix0);
        const int iy1 = iy0 + 1 > 511 ? 511 : iy0 + 1;
        const int ix1 = ix0 + 1 > 511 ? 511 : ix0 + 1;

        const size_t base = (size_t)b * IMG_H * IMG_W;
        const float p00 = prop[base + (size_t)iy0 * IMG_W + ix0];
        const float p01 = prop[base + (size_t)iy0 * IMG_W + ix1];
        const float p10 = prop[base + (size_t)iy1 * IMG_W + ix0];
        const float p11 = prop[base + (size_t)iy1 * IMG_W + ix1];
        const float omwx = 1.f - wx, omwy = 1.f - wy;
        const float pv = (p00 * omwx + p01 * wx) * omwy
                       + (p10 * omwx + p11 * wx) * wy;

        const float4* f00 = (const float4*)(feat + (base + (size_t)iy0 * IMG_W + ix0) * IMG_C);
        const float4* f01 = (const float4*)(feat + (base + (size_t)iy0 * IMG_W + ix1) * IMG_C);
        const float4* f10 = (const float4*)(feat + (base + (size_t)iy1 * IMG_W + ix0) * IMG_C);
        const float4* f11 = (const float4*)(feat + (base + (size_t)iy1 * IMG_W + ix1) * IMG_C);
        float4* dst = (float4*)(s_x0 + t * 64);
        #pragma unroll
        for (int cb = 0; cb < 16; cb++) {
            float4 a = f00[cb], c = f01[cb], d = f10[cb], e = f11[cb];
            float4 r;
            r.x = ((a.x * omwx + c.x * wx) * omwy + (d.x * omwx + e.x * wx) * wy) * pv;
            r.y = ((a.y * omwx + c.y * wx) * omwy + (d.y * omwx + e.y * wx) * wy) * pv;
            r.z = ((a.z * omwx + c.z * wx) * omwy + (d.z * omwx + e.z * wx) * wy) * pv;
            r.w = ((a.w * omwx + c.w * wx) * omwy + (d.w * omwx + e.w * wx) * wy) * pv;
            dst[cb] = r;
        }
    }
    __syncthreads();

    // ---- Stage 2: conv1 3x3 s2 SAME (pad lo=0, hi=1), 64->128, relu ----
    // thread: g1 = t&31 -> ocs [g1*4, g1*4+4) (2 packed pairs)
    //         s1 = t>>5 -> 8 positions [s1*8, s1*8+8)  (warp-uniform -> LDS bcast)
    {
        const int g1 = t & 31;
        const int oc0 = g1 * 4;
        const int s1 = t >> 5;

        ull acc[8][2];
        {
            float4 bb = __ldg((const float4*)(b1 + oc0));
            ull p0 = pack2(bb.x, bb.y), p1 = pack2(bb.z, bb.w);
            #pragma unroll
            for (int j = 0; j < 8; j++) { acc[j][0] = p0; acc[j][1] = p1; }
        }

        #pragma unroll 1
        for (int tap = 0; tap < 9; tap++) {
            const int ky = tap / 3, kx = tap % 3;
            int ib[8];
            #pragma unroll
            for (int j = 0; j < 8; j++) {
                const int pos = s1 * 8 + j;
                const int oy = pos >> 3, ox = pos & 7;
                const int iy = 2 * oy + ky, ix = 2 * ox + kx;
                ib[j] = (iy < 16 && ix < 16) ? (iy * 16 + ix) * 64 : -1;
            }
            const float* wt = w1 + (size_t)(tap * 64) * 128 + oc0;
            #pragma unroll 2
            for (int ic = 0; ic < 64; ic += 4) {
                const float* wb = wt + (size_t)ic * 128;
                ulonglong2 w0 = __ldg((const ulonglong2*)(wb));
                ulonglong2 w1v = __ldg((const ulonglong2*)(wb + 128));
                ulonglong2 w2v = __ldg((const ulonglong2*)(wb + 256));
                ulonglong2 w3v = __ldg((const ulonglong2*)(wb + 384));
                #pragma unroll
                for (int j = 0; j < 8; j++) {
                    if (ib[j] >= 0) {
                        float4 v = *(const float4*)(s_x0 + ib[j] + ic);
                        ull dx = dup2(v.x), dy = dup2(v.y), dz = dup2(v.z), dw = dup2(v.w);
                        acc[j][0] = fma2(dx, w0.x, acc[j][0]);
                        acc[j][1] = fma2(dx, w0.y, acc[j][1]);
                        acc[j][0] = fma2(dy, w1v.x, acc[j][0]);
                        acc[j][1] = fma2(dy, w1v.y, acc[j][1]);
                        acc[j][0] = fma2(dz, w2v.x, acc[j][0]);
                        acc[j][1] = fma2(dz, w2v.y, acc[j][1]);
                        acc[j][0] = fma2(dw, w3v.x, acc[j][0]);
                        acc[j][1] = fma2(dw, w3v.y, acc[j][1]);
                    }
                }
            }
        }
        #pragma unroll
        for (int j = 0; j < 8; j++) {
            const int pos = s1 * 8 + j;
            float v0, v1, v2, v3;
            unpack2(acc[j][0], v0, v1); unpack2(acc[j][1], v2, v3);
            *(float4*)(s_c1 + pos * 128 + oc0) =
                make_float4(fmaxf(v0, 0.f), fmaxf(v1, 0.f),
                            fmaxf(v2, 0.f), fmaxf(v3, 0.f));
        }
    }
    __syncthreads();

    // ---- Stage 3: conv2 3x3 s2 SAME (pad lo=0, hi=1), 128->128, relu ----
    // thread: p2 = t&63 -> oc pair [p2*2, p2*2+2)
    //         s2 = t>>6 -> 4 positions [s2*4, s2*4+4)
    {
        const int p2 = t & 63;
        const int oc0 = p2 * 2;
        const int s2 = t >> 6;

        ull acc2[4];
        {
            ull bb = __ldg((const ull*)(b2 + oc0));
            #pragma unroll
            for (int j = 0; j < 4; j++) acc2[j] = bb;
        }

        #pragma unroll 1
        for (int tap = 0; tap < 9; tap++) {
            const int ky = tap / 3, kx = tap % 3;
            int ib[4];
            #pragma unroll
            for (int j = 0; j < 4; j++) {
                const int pos = s2 * 4 + j;
                const int oy = pos >> 2, ox = pos & 3;
                const int iy = 2 * oy + ky, ix = 2 * ox + kx;
                ib[j] = (iy < 8 && ix < 8) ? (iy * 8 + ix) * 128 : -1;
            }
            const float* wt = w2 + (size_t)(tap * 128) * 128 + oc0;
            #pragma unroll 2
            for (int ic = 0; ic < 128; ic += 4) {
                const float* wb = wt + (size_t)ic * 128;
                ull w0 = __ldg((const ull*)(wb));
                ull w1v = __ldg((const ull*)(wb + 128));
                ull w2v = __ldg((const ull*)(wb + 256));
                ull w3v = __ldg((const ull*)(wb + 384));
                #pragma unroll
                for (int j = 0; j < 4; j++) {
                    if (ib[j] >= 0) {
                        float4 v = *(const float4*)(s_c1 + ib[j] + ic);
                        acc2[j] = fma2(dup2(v.x), w0, acc2[j]);
                        acc2[j] = fma2(dup2(v.y), w1v, acc2[j]);
                        acc2[j] = fma2(dup2(v.z), w2v, acc2[j]);
                        acc2[j] = fma2(dup2(v.w), w3v, acc2[j]);
                    }
                }
            }
        }
        float* o = xout + (size_t)box * 2048;
        #pragma unroll
        for (int j = 0; j < 4; j++) {
            const int pos = s2 * 4 + j;
            float v0, v1;
            unpack2(acc2[j], v0, v1);
            *(float2*)(o + pos * 128 + oc0) =
                make_float2(fmaxf(v0, 0.f), fmaxf(v1, 0.f));
        }
    }
}

// ---------------------------------------------------------------------------
// GEMM: C[M,N] = act(A[M,K] @ B[K,N] + bias). 64x64 tile, 256 threads, 4x4/thr.
// Register double-buffered global loads (hide LDG latency behind compute).
// ---------------------------------------------------------------------------
template <int RELU>
__global__ __launch_bounds__(256) void k_gemm(
    const float* __restrict__ A, const float* __restrict__ Bm,
    const float* __restrict__ bias, float* __restrict__ Cm,
    int M, int N, int K)
{
    __shared__ float As[16][68];   // [k][m] — m contiguous
    __shared__ float Bs[16][68];   // [k][n] — n contiguous
    const int tid = threadIdx.x;
    const int m0 = blockIdx.x * 64, n0 = blockIdx.y * 64;
    const int tr = tid >> 4, tc = tid & 15;
    const int lam = tid >> 2, lak = (tid & 3) * 4;
    const int lbk = tid >> 4, lbn = (tid & 15) * 4;

    ull accp[2][4];
    #pragma unroll
    for (int i = 0; i < 2; i++)
        #pragma unroll
        for (int j = 0; j < 4; j++) accp[i][j] = 0ull;

    const float* Ap = A + (size_t)(m0 + lam) * K + lak;
    const float* Bp = Bm + (size_t)lbk * N + n0 + lbn;

    float4 a = *(const float4*)(Ap);
    float4 bv = *(const float4*)(Bp);

    for (int k0 = 0; k0 < K; k0 += 16) {
        __syncthreads();
        As[lak + 0][lam] = a.x; As[lak + 1][lam] = a.y;
        As[lak + 2][lam] = a.z; As[lak + 3][lam] = a.w;
        *(float4*)&Bs[lbk][lbn] = bv;
        __syncthreads();
        if (k0 + 16 < K) {   // prefetch next tile while computing this one
            a = *(const float4*)(Ap + k0 + 16);
            bv = *(const float4*)(Bp + (size_t)(k0 + 16) * N);
        }
        #pragma unroll
        for (int k = 0; k < 16; k++) {
            ulonglong2 ap = *(const ulonglong2*)&As[k][tr * 4];
            float4 bb = *(const float4*)&Bs[k][tc * 4];
            ull b0 = dup2(bb.x), b1 = dup2(bb.y), b2 = dup2(bb.z), b3 = dup2(bb.w);
            accp[0][0] = fma2(ap.x, b0, accp[0][0]);
            accp[0][1] = fma2(ap.x, b1, accp[0][1]);
            accp[0][2] = fma2(ap.x, b2, accp[0][2]);
            accp[0][3] = fma2(ap.x, b3, accp[0][3]);
            accp[1][0] = fma2(ap.y, b0, accp[1][0]);
            accp[1][1] = fma2(ap.y, b1, accp[1][1]);
            accp[1][2] = fma2(ap.y, b2, accp[1][2]);
            accp[1][3] = fma2(ap.y, b3, accp[1][3]);
        }
    }

    float4 bvq = __ldg((const float4*)(bias + n0 + tc * 4));
    float bias4[4] = {bvq.x, bvq.y, bvq.z, bvq.w};
    #pragma unroll
    for (int ih = 0; ih < 2; ih++) {
        float r0[4], r1[4];
        #pragma unroll
        for (int j = 0; j < 4; j++) unpack2(accp[ih][j], r0[j], r1[j]);
        #pragma unroll
        for (int j = 0; j < 4; j++) {
            r0[j] += bias4[j]; r1[j] += bias4[j];
            if (RELU) { r0[j] = fmaxf(r0[j], 0.f); r1[j] = fmaxf(r1[j], 0.f); }
        }
        const int row0 = m0 + tr * 4 + 2 * ih;
        *(float4*)(Cm + (size_t)row0 * N + n0 + tc * 4) =
            make_float4(r0[0], r0[1], r0[2], r0[3]);
        *(float4*)(Cm + (size_t)(row0 + 1) * N + n0 + tc * 4) =
            make_float4(r1[0], r1[1], r1[2], r1[3]);
    }
}

// ---------------------------------------------------------------------------
// K4: heads — reg/score dots (warp per box), class select, box decode.
// out = [scores (Nb) | regressions (Nb*4) | bboxes (Nb*4)]
// ---------------------------------------------------------------------------
__global__ __launch_bounds__(256) void k_heads(
    const float* __restrict__ X, const float* __restrict__ boxes,
    const int* __restrict__ cls, const float* __restrict__ regw,
    const float* __restrict__ regb, const float* __restrict__ scw,
    const float* __restrict__ scb, float* __restrict__ out, int Nb)
{
    const int gw = (blockIdx.x * blockDim.x + threadIdx.x) >> 5;
    const int lane = threadIdx.x & 31;
    if (gw >= Nb) return;
    const float* x = X + (size_t)gw * 512;

    float acc[12], sc[3];
    #pragma unroll
    for (int c = 0; c < 12; c++) acc[c] = 0.f;
    #pragma unroll
    for (int c = 0; c < 3; c++) sc[c] = 0.f;

    for (int j = lane; j < 512; j += 32) {
        float xv = x[j];
        const float* wr = regw + j * 12;
        #pragma unroll
        for (int c = 0; c < 12; c++) acc[c] = fmaf(xv, __ldg(wr + c), acc[c]);
        const float* ws = scw + j * 3;
        #pragma unroll
        for (int c = 0; c < 3; c++) sc[c] = fmaf(xv, __ldg(ws + c), sc[c]);
    }
    #pragma unroll
    for (int c = 0; c < 12; c++)
        for (int s = 16; s; s >>= 1) acc[c] += __shfl_xor_sync(0xffffffffu, acc[c], s);
    #pragma unroll
    for (int c = 0; c < 3; c++)
        for (int s = 16; s; s >>= 1) sc[c] += __shfl_xor_sync(0xffffffffu, sc[c], s);

    if (lane == 0) {
        const int cl = cls[gw];
        float r[4];
        #pragma unroll
        for (int k = 0; k < 4; k++) {
            float v = (cl == 0) ? acc[k] : (cl == 1) ? acc[4 + k] : acc[8 + k];
            r[k] = v + regb[cl * 4 + k];
        }
        float score = ((cl == 0) ? sc[0] : (cl == 1) ? sc[1] : sc[2]) + scb[cl];

        const float y1 = boxes[gw * 4 + 0], x1 = boxes[gw * 4 + 1];
        const float y2 = boxes[gw * 4 + 2], x2 = boxes[gw * 4 + 3];
        const float h = y2 - y1, w = x2 - x1;
        const float cy = y1 + 0.5f * h + r[0] * h;
        const float cx = x1 + 0.5f * w + r[1] * w;
        const float nh = h * expf(r[2]);
        const float nw = w * expf(r[3]);

        out[gw] = score;
        float* ro = out + Nb + (size_t)gw * 4;
        ro[0] = r[0]; ro[1] = r[1]; ro[2] = r[2]; ro[3] = r[3];
        float* bo = out + (size_t)Nb * 5 + (size_t)gw * 4;
        bo[0] = cy - 0.5f * nh; bo[1] = cx - 0.5f * nw;
        bo[2] = cy + 0.5f * nh; bo[3] = cx + 0.5f * nw;
    }
}

// ---------------------------------------------------------------------------
extern "C" void kernel_launch(void* const* d_in, const int* in_sizes, int n_in,
                              void* d_out, int out_size)
{
    const float* features = (const float*)d_in[0];
    const float* proposal = (const float*)d_in[1];
    const float* bboxes   = (const float*)d_in[2];
    const int*   box_idx  = (const int*)d_in[3];
    const int*   cls      = (const int*)d_in[4];
    const float* c1w      = (const float*)d_in[5];
    const float* c1b      = (const float*)d_in[6];
    const float* c2w      = (const float*)d_in[7];
    const float* c2b      = (const float*)d_in[8];
    const float* d1w      = (const float*)d_in[9];
    const float* d1b      = (const float*)d_in[10];
    const float* d2w      = (const float*)d_in[11];
    const float* d2b      = (const float*)d_in[12];
    const float* regw     = (const float*)d_in[13];
    const float* regb     = (const float*)d_in[14];
    const float* scw      = (const float*)d_in[15];
    const float* scb      = (const float*)d_in[16];
    float* out = (float*)d_out;

    const int Nb = in_sizes[3];  // number of boxes (4096)

    void *px1, *ph1, *ph2;
    cudaGetSymbolAddress(&px1, g_x1);
    cudaGetSymbolAddress(&ph1, g_h1);
    cudaGetSymbolAddress(&ph2, g_h2);

    const int smem_k1 = (16 * 16 * 64 + 8 * 8 * 128) * 4;  // 98304 bytes
    cudaFuncSetAttribute(k_backbone, cudaFuncAttributeMaxDynamicSharedMemorySize, smem_k1);

    // Shift ncu's skip window (-s 5) so the profiled launch is k_backbone,
    // not k_heads. Negligible cost; removable once backbone data is captured.
    k_nop<<<1, 32>>>();
    k_nop<<<1, 32>>>();
    k_nop<<<1, 32>>>();

    k_backbone<<<Nb, 256, smem_k1>>>(features, proposal, bboxes, box_idx,
                                     c1w, c1b, c2w, c2b, (float*)px1);

    k_gemm<1><<<dim3(Nb / 64, 512 / 64), 256>>>((const float*)px1, d1w, d1b,
                                                (float*)ph1, Nb, 512, 2048);
    k_gemm<1><<<dim3(Nb / 64, 512 / 64), 256>>>((const float*)ph1, d2w, d2b,
                                                (float*)ph2, Nb, 512, 512);

    k_heads<<<(Nb * 32 + 255) / 256, 256>>>((const float*)ph2, bboxes, cls,
                                            regw, regb, scw, scb, out, Nb);
}